// round 14
// baseline (speedup 1.0000x reference)
#include <cuda_runtime.h>
#include <cuda_fp16.h>
#include <cstdint>

// ---------------- problem constants ----------------
#define N_TOK  2048
#define D_IN   2048
#define D_OUT  2048
#define N_EXP  8
#define TOPK   2
#define NK     (N_TOK * TOPK)        // 4096 rows

// ---------------- tiling ----------------
#define BM 128
#define BN 256
#define BK 64                        // k halfs per stage (128 B per row)
#define STAGES 4
#define SPLITK 2
#define KSPLIT (D_IN / SPLITK)       // 1024 halfs per split
#define KITERS (KSPLIT / BK)         // 16 per split
#define MT (NK / BM)                 // 32 m-tiles per expert worst case
#define ROWB 128u
#define STAGE_BYTES ((BM + BN) * 128)    // 49152 B per stage
#define NTHREADS 256                 // 8 warps; 2(m) x 4(n) grid of 64x64 warp tiles

// ---------------- scratch ----------------
__device__ __half g_xh[(size_t)(NK + BM) * D_IN];     // gathered fp16 X rows
__device__ __half g_wh[(size_t)N_EXP * D_OUT * D_IN]; // fp16 weights (67 MB)

// ---------------- prep: gather rows into sorted order + fp16 convert ----------------
__global__ void prep(const float* __restrict__ X, const int* __restrict__ scat) {
    const int p = blockIdx.x;
    const int tok = scat[p] / TOPK;
    const float4* src = (const float4*)(X + (size_t)tok * D_IN);
    uint4* dst = (uint4*)(g_xh + (size_t)p * D_IN);
    const int t = threadIdx.x;
    float4 v0 = src[2 * t], v1 = src[2 * t + 1];
    __half2 h0 = __floats2half2_rn(v0.x, v0.y);
    __half2 h1 = __floats2half2_rn(v0.z, v0.w);
    __half2 h2 = __floats2half2_rn(v1.x, v1.y);
    __half2 h3 = __floats2half2_rn(v1.z, v1.w);
    uint4 o;
    o.x = *(uint32_t*)&h0; o.y = *(uint32_t*)&h1;
    o.z = *(uint32_t*)&h2; o.w = *(uint32_t*)&h3;
    dst[t] = o;
}

// ---------------- W -> fp16 (RN), deep-MLP streaming ----------------
#define CVTW_BLOCKS 2048
#define CVTW_PER_THREAD 8
static_assert((size_t)CVTW_BLOCKS * 256 * CVTW_PER_THREAD ==
              (size_t)N_EXP * D_OUT * D_IN / 8, "cvtW grid must cover all of W");

__global__ void cvtW(const float* __restrict__ W) {
    const size_t stride = (size_t)CVTW_BLOCKS * 256;
    size_t i = (size_t)blockIdx.x * 256 + threadIdx.x;
    float4 v[CVTW_PER_THREAD][2];
    size_t idx[CVTW_PER_THREAD];
    #pragma unroll
    for (int q = 0; q < CVTW_PER_THREAD; q++) {
        idx[q] = i + q * stride;
        const float4* src = (const float4*)(W + idx[q] * 8);
        v[q][0] = __ldcs(src);
        v[q][1] = __ldcs(src + 1);
    }
    #pragma unroll
    for (int q = 0; q < CVTW_PER_THREAD; q++) {
        __half2 h0 = __floats2half2_rn(v[q][0].x, v[q][0].y);
        __half2 h1 = __floats2half2_rn(v[q][0].z, v[q][0].w);
        __half2 h2 = __floats2half2_rn(v[q][1].x, v[q][1].y);
        __half2 h3 = __floats2half2_rn(v[q][1].z, v[q][1].w);
        uint4 o;
        o.x = *(uint32_t*)&h0; o.y = *(uint32_t*)&h1;
        o.z = *(uint32_t*)&h2; o.w = *(uint32_t*)&h3;
        *(uint4*)(g_wh + idx[q] * 8) = o;
    }
}

__device__ __forceinline__ uint32_t swz_off(uint32_t r, uint32_t chunk) {
    return r * ROWB + (((chunk ^ (r & 7u))) << 4);
}

// ---------------- main grouped GEMM: split-K, CTA 128x256, warp tile 64x64 ----------------
__global__ __launch_bounds__(NTHREADS, 1) void moe_mma(
    const int*   __restrict__ scat,
    const int*   __restrict__ offs,
    const float* __restrict__ gates,
    float*       __restrict__ out)
{
    const int e     = blockIdx.y / MT;
    const int mt    = blockIdx.y % MT;
    const int start = (e == 0) ? 0 : offs[e - 1];
    const int end   = offs[e];
    const int row0  = start + mt * BM;
    if (row0 >= end) return;
    const int n0 = blockIdx.x * BN;
    const int k0 = blockIdx.z * KSPLIT;        // this CTA's k-range start (halfs)

    extern __shared__ uint32_t sm[];
    __shared__ int   s_tok[BM];
    __shared__ float s_gate[BM];

    const int tid  = threadIdx.x;
    const int warp = tid >> 5;
    const int lane = tid & 31;

    if (tid < BM) {
        int p = row0 + tid; int tok = 0; float g = 0.0f;
        if (p < end) { int j = scat[p]; tok = j / TOPK; g = gates[j]; }
        s_tok[tid] = tok; s_gate[tid] = g;
    }

    // ---- global->smem mapping (offset by k0) ----
    const __half* gA = g_xh + (size_t)(row0 + (tid & 127)) * D_IN + k0;  // tid<128 only
    const __half* gB = g_wh + (size_t)e * D_OUT * D_IN + (size_t)(n0 + tid) * D_IN + k0;

    const uint32_t smb = (uint32_t)__cvta_generic_to_shared(sm);
    uint32_t dstA[8], dstB[8];
    #pragma unroll
    for (int q = 0; q < 8; q++) {
        dstA[q] = swz_off((uint32_t)(tid & 127), (uint32_t)q);
        dstB[q] = swz_off((uint32_t)(BM + tid), (uint32_t)q);
    }
    const bool hasA = tid < BM;

    #define LOAD_STAGE(st, it)                                                        \
        do {                                                                          \
            uint32_t _s = smb + (uint32_t)(st) * STAGE_BYTES;                         \
            const __half* _gb = gB + (size_t)(it) * BK;                               \
            _Pragma("unroll")                                                         \
            for (int q = 0; q < 8; q++) {                                             \
                asm volatile("cp.async.cg.shared.global [%0], [%1], 16;"              \
                             :: "r"(_s + dstB[q]), "l"(_gb + q * 8) : "memory");      \
            }                                                                         \
            if (hasA) {                                                               \
                const __half* _ga = gA + (size_t)(it) * BK;                           \
                _Pragma("unroll")                                                     \
                for (int q = 0; q < 8; q++) {                                         \
                    asm volatile("cp.async.cg.shared.global [%0], [%1], 16;"          \
                                 :: "r"(_s + dstA[q]), "l"(_ga + q * 8) : "memory");  \
                }                                                                     \
            }                                                                         \
        } while (0)

    LOAD_STAGE(0, 0);
    asm volatile("cp.async.commit_group;" ::: "memory");
    LOAD_STAGE(1, 1);
    asm volatile("cp.async.commit_group;" ::: "memory");
    LOAD_STAGE(2, 2);
    asm volatile("cp.async.commit_group;" ::: "memory");

    // ---- fragment geometry: 2(m) x 4(n) warps, warp tile 64x64 ----
    const int wm = warp >> 2;
    const int wn = warp & 3;
    const int g4 = lane >> 2;
    const int tg = lane & 3;
    const int x7 = lane & 7;
    const uint32_t ar  = (uint32_t)(wm * 64 + (lane & 15));
    const uint32_t as  = (uint32_t)(lane >> 4);
    const uint32_t br4 = (uint32_t)(BM + wn * 64 + ((lane >> 4) << 3) + x7);
    const uint32_t bs4 = (uint32_t)((lane >> 3) & 1);
    uint32_t aoff[4], boff[4];
    #pragma unroll
    for (int kk = 0; kk < 4; kk++) {
        aoff[kk] = (uint32_t)(((2 * kk + (int)as)  ^ x7) << 4);
        boff[kk] = (uint32_t)(((2 * kk + (int)bs4) ^ x7) << 4);
    }

    float acc[4][8][4];
    #pragma unroll
    for (int i = 0; i < 4; i++)
        #pragma unroll
        for (int j = 0; j < 8; j++)
            #pragma unroll
            for (int q = 0; q < 4; q++) acc[i][j][q] = 0.0f;

    #define LD_FRAGS(kk, A, B)                                                        \
        do {                                                                          \
            _Pragma("unroll")                                                         \
            for (int mi = 0; mi < 4; mi++) {                                          \
                uint32_t _ad = sS + (ar + (uint32_t)(mi * 16)) * ROWB + aoff[kk];     \
                asm volatile(                                                         \
                    "ldmatrix.sync.aligned.m8n8.x4.shared.b16 {%0,%1,%2,%3}, [%4];"   \
                    : "=r"(A[mi][0]), "=r"(A[mi][1]), "=r"(A[mi][2]), "=r"(A[mi][3])  \
                    : "r"(_ad));                                                      \
            }                                                                         \
            _Pragma("unroll")                                                         \
            for (int njp = 0; njp < 4; njp++) {                                       \
                uint32_t _bd = sS + (br4 + (uint32_t)(njp * 16)) * ROWB + boff[kk];   \
                asm volatile(                                                         \
                    "ldmatrix.sync.aligned.m8n8.x4.shared.b16 {%0,%1,%2,%3}, [%4];"   \
                    : "=r"(B[2*njp][0]), "=r"(B[2*njp][1]),                           \
                      "=r"(B[2*njp+1][0]), "=r"(B[2*njp+1][1])                        \
                    : "r"(_bd));                                                      \
            }                                                                         \
        } while (0)

    #define DO_MMAS(A, B)                                                             \
        do {                                                                          \
            _Pragma("unroll")                                                         \
            for (int mi = 0; mi < 4; mi++)                                            \
                _Pragma("unroll")                                                     \
                for (int nj = 0; nj < 8; nj++) {                                      \
                    float* cc = acc[mi][nj];                                          \
                    asm volatile(                                                     \
                        "mma.sync.aligned.m16n8k16.row.col.f32.f16.f16.f32 "          \
                        "{%0,%1,%2,%3}, {%4,%5,%6,%7}, {%8,%9}, {%0,%1,%2,%3};\n"     \
                        : "+f"(cc[0]), "+f"(cc[1]), "+f"(cc[2]), "+f"(cc[3])          \
                        : "r"(A[mi][0]), "r"(A[mi][1]), "r"(A[mi][2]), "r"(A[mi][3]), \
                          "r"(B[nj][0]), "r"(B[nj][1]));                              \
                }                                                                     \
        } while (0)

    __syncthreads();   // s_tok/s_gate visible

    #pragma unroll 1
    for (int it = 0; it < KITERS; it++) {
        // 3 groups outstanding {it,it+1,it+2}; drain group it
        asm volatile("cp.async.wait_group 2;" ::: "memory");
        __syncthreads();   // all warps past iter it-1 -> stage (it+3)%4 free; stage it ready

        if (it + 3 < KITERS) LOAD_STAGE((it + 3) % STAGES, it + 3);
        asm volatile("cp.async.commit_group;" ::: "memory");

        const int st = it % STAGES;
        const uint32_t sS = smb + (uint32_t)st * STAGE_BYTES;

        uint32_t a0[4][4], b0[8][2], a1[4][4], b1[8][2];
        LD_FRAGS(0, a0, b0);
        LD_FRAGS(1, a1, b1);
        DO_MMAS(a0, b0);
        LD_FRAGS(2, a0, b0);
        DO_MMAS(a1, b1);
        LD_FRAGS(3, a1, b1);
        DO_MMAS(a0, b0);
        DO_MMAS(a1, b1);
    }

    // ---- epilogue: gate-scaled atomic accumulate (linear in k-splits) ----
    #pragma unroll
    for (int mi = 0; mi < 4; mi++) {
        #pragma unroll
        for (int half = 0; half < 2; half++) {
            const int r = wm * 64 + mi * 16 + g4 + half * 8;
            const int p = row0 + r;
            if (p < end) {
                const float g = s_gate[r];
                float* orow = out + (size_t)s_tok[r] * D_OUT + n0;
                #pragma unroll
                for (int nj = 0; nj < 8; nj++) {
                    const int col = wn * 64 + nj * 8 + 2 * tg;
                    atomicAdd(&orow[col    ], g * acc[mi][nj][half * 2 + 0]);
                    atomicAdd(&orow[col + 1], g * acc[mi][nj][half * 2 + 1]);
                }
            }
        }
    }
}

// ---------------- launch ----------------
extern "C" void kernel_launch(void* const* d_in, const int* in_sizes, int n_in,
                              void* d_out, int out_size)
{
    const float* X = (const float*)d_in[0];
    const float* W = (const float*)d_in[1];
    const int *scat, *offs; const float* gates;
    if (n_in >= 8) {
        scat = (const int*)d_in[4]; offs = (const int*)d_in[6]; gates = (const float*)d_in[7];
    } else {
        scat = (const int*)d_in[3]; offs = (const int*)d_in[5]; gates = (const float*)d_in[6];
    }
    float* out = (float*)d_out;

    cvtW<<<CVTW_BLOCKS, 256>>>(W);
    prep<<<NK, 256>>>(X, scat);
    cudaMemsetAsync(out, 0, (size_t)N_TOK * D_OUT * sizeof(float));

    const int dyn_smem = STAGES * STAGE_BYTES;   // 196608 B
    static bool attr_set = false;
    if (!attr_set) {
        cudaFuncSetAttribute(moe_mma, cudaFuncAttributeMaxDynamicSharedMemorySize, dyn_smem);
        attr_set = true;
    }

    dim3 grid(D_OUT / BN, N_EXP * MT, SPLITK);   // 8 x 256 x 2
    moe_mma<<<grid, NTHREADS, dyn_smem>>>(scat, offs, gates, out);
}

// round 17
// speedup vs baseline: 1.0835x; 1.0835x over previous
#include <cuda_runtime.h>
#include <cuda_fp16.h>
#include <cstdint>

// ---------------- problem constants ----------------
#define N_TOK  2048
#define D_IN   2048
#define D_OUT  2048
#define N_EXP  8
#define TOPK   2
#define NK     (N_TOK * TOPK)        // 4096 rows

// ---------------- tiling ----------------
#define BM 128
#define BN 256
#define BK 64                        // k halfs per stage (128 B per row)
#define STAGES 4
#define KITERS (D_IN / BK)           // 32
#define MT (NK / BM)                 // 32 m-tiles per expert worst case
#define ROWB 128u
#define STAGE_BYTES ((BM + BN) * 128)    // 49152 B per stage
#define NTHREADS 256                 // 8 warps; 2(m) x 4(n) grid of 64x64 warp tiles

// ---------------- scratch ----------------
__device__ __half g_xh[(size_t)(NK + BM) * D_IN];     // gathered fp16 X rows
__device__ __half g_wh[(size_t)N_EXP * D_OUT * D_IN]; // fp16 weights (67 MB)

// ---------------- fused preprocessing: W->fp16 | X gather->fp16 | zero(out) ----------------
#define PRE_W_BLOCKS 2048
#define PRE_W_PER_THREAD 8
#define PRE_X_BLOCKS NK              // 4096
#define PRE_Z_BLOCKS 1024
static_assert((size_t)PRE_W_BLOCKS * 256 * PRE_W_PER_THREAD ==
              (size_t)N_EXP * D_OUT * D_IN / 8, "W range must cover all of W");
static_assert((size_t)PRE_Z_BLOCKS * 256 * 4 ==
              (size_t)N_TOK * D_OUT / 4, "zero range must cover all of out");

__global__ void preproc(const float* __restrict__ X,
                        const float* __restrict__ W,
                        const int*   __restrict__ scat,
                        float*       __restrict__ out)
{
    const int bid = blockIdx.x;
    const int t   = threadIdx.x;

    if (bid < PRE_W_BLOCKS) {
        // ---- W -> fp16 (RN), deep-MLP streaming ----
        const size_t stride = (size_t)PRE_W_BLOCKS * 256;
        size_t i = (size_t)bid * 256 + t;
        float4 v[PRE_W_PER_THREAD][2];
        size_t idx[PRE_W_PER_THREAD];
        #pragma unroll
        for (int q = 0; q < PRE_W_PER_THREAD; q++) {
            idx[q] = i + q * stride;
            const float4* src = (const float4*)(W + idx[q] * 8);
            v[q][0] = __ldcs(src);
            v[q][1] = __ldcs(src + 1);
        }
        #pragma unroll
        for (int q = 0; q < PRE_W_PER_THREAD; q++) {
            __half2 h0 = __floats2half2_rn(v[q][0].x, v[q][0].y);
            __half2 h1 = __floats2half2_rn(v[q][0].z, v[q][0].w);
            __half2 h2 = __floats2half2_rn(v[q][1].x, v[q][1].y);
            __half2 h3 = __floats2half2_rn(v[q][1].z, v[q][1].w);
            uint4 o;
            o.x = *(uint32_t*)&h0; o.y = *(uint32_t*)&h1;
            o.z = *(uint32_t*)&h2; o.w = *(uint32_t*)&h3;
            *(uint4*)(g_wh + idx[q] * 8) = o;
        }
    } else if (bid < PRE_W_BLOCKS + PRE_X_BLOCKS) {
        // ---- gather X rows into sorted order + fp16 convert ----
        const int p = bid - PRE_W_BLOCKS;
        const int tok = scat[p] / TOPK;
        const float4* src = (const float4*)(X + (size_t)tok * D_IN);
        uint4* dst = (uint4*)(g_xh + (size_t)p * D_IN);
        float4 v0 = src[2 * t], v1 = src[2 * t + 1];
        __half2 h0 = __floats2half2_rn(v0.x, v0.y);
        __half2 h1 = __floats2half2_rn(v0.z, v0.w);
        __half2 h2 = __floats2half2_rn(v1.x, v1.y);
        __half2 h3 = __floats2half2_rn(v1.z, v1.w);
        uint4 o;
        o.x = *(uint32_t*)&h0; o.y = *(uint32_t*)&h1;
        o.z = *(uint32_t*)&h2; o.w = *(uint32_t*)&h3;
        dst[t] = o;
    } else {
        // ---- zero out (atomic accumulate target) ----
        const int zb = bid - PRE_W_BLOCKS - PRE_X_BLOCKS;
        const size_t stride = (size_t)PRE_Z_BLOCKS * 256;
        size_t i = (size_t)zb * 256 + t;
        const uint4 z = make_uint4(0u, 0u, 0u, 0u);
        uint4* o4 = (uint4*)out;
        #pragma unroll
        for (int q = 0; q < 4; q++)
            o4[i + q * stride] = z;
    }
}

__device__ __forceinline__ uint32_t swz_off(uint32_t r, uint32_t chunk) {
    return r * ROWB + (((chunk ^ (r & 7u))) << 4);
}

// ---------------- main grouped GEMM: 256 threads, CTA 128x256, warp tile 64x64 ----------------
__global__ __launch_bounds__(NTHREADS, 1) void moe_mma(
    const int*   __restrict__ scat,
    const int*   __restrict__ offs,
    const float* __restrict__ gates,
    float*       __restrict__ out)
{
    const int e     = blockIdx.y / MT;
    const int mt    = blockIdx.y % MT;
    const int start = (e == 0) ? 0 : offs[e - 1];
    const int end   = offs[e];
    const int row0  = start + mt * BM;
    if (row0 >= end) return;
    const int n0 = blockIdx.x * BN;

    extern __shared__ uint32_t sm[];
    __shared__ int   s_tok[BM];
    __shared__ float s_gate[BM];

    const int tid  = threadIdx.x;
    const int warp = tid >> 5;
    const int lane = tid & 31;

    if (tid < BM) {
        int p = row0 + tid; int tok = 0; float g = 0.0f;
        if (p < end) { int j = scat[p]; tok = j / TOPK; g = gates[j]; }
        s_tok[tid] = tok; s_gate[tid] = g;
    }

    // ---- global->smem: every thread loads one B row; threads 0-127 also one A row ----
    const __half* gA = g_xh + (size_t)(row0 + (tid & 127)) * D_IN;     // valid for tid<128
    const __half* gB = g_wh + (size_t)e * D_OUT * D_IN + (size_t)(n0 + tid) * D_IN;

    const uint32_t smb = (uint32_t)__cvta_generic_to_shared(sm);
    uint32_t dstA[8], dstB[8];
    #pragma unroll
    for (int q = 0; q < 8; q++) {
        dstA[q] = swz_off((uint32_t)(tid & 127), (uint32_t)q);
        dstB[q] = swz_off((uint32_t)(BM + tid), (uint32_t)q);
    }
    const bool hasA = tid < BM;

    #define LOAD_STAGE(st, it)                                                        \
        do {                                                                          \
            uint32_t _s = smb + (uint32_t)(st) * STAGE_BYTES;                         \
            const __half* _gb = gB + (size_t)(it) * BK;                               \
            _Pragma("unroll")                                                         \
            for (int q = 0; q < 8; q++) {                                             \
                asm volatile("cp.async.cg.shared.global [%0], [%1], 16;"              \
                             :: "r"(_s + dstB[q]), "l"(_gb + q * 8) : "memory");      \
            }                                                                         \
            if (hasA) {                                                               \
                const __half* _ga = gA + (size_t)(it) * BK;                           \
                _Pragma("unroll")                                                     \
                for (int q = 0; q < 8; q++) {                                         \
                    asm volatile("cp.async.cg.shared.global [%0], [%1], 16;"          \
                                 :: "r"(_s + dstA[q]), "l"(_ga + q * 8) : "memory");  \
                }                                                                     \
            }                                                                         \
        } while (0)

    LOAD_STAGE(0, 0);
    asm volatile("cp.async.commit_group;" ::: "memory");
    LOAD_STAGE(1, 1);
    asm volatile("cp.async.commit_group;" ::: "memory");
    LOAD_STAGE(2, 2);
    asm volatile("cp.async.commit_group;" ::: "memory");

    // ---- fragment geometry: 2(m) x 4(n) warps, warp tile 64x64 ----
    const int wm = warp >> 2;
    const int wn = warp & 3;
    const int g4 = lane >> 2;
    const int tg = lane & 3;
    const int x7 = lane & 7;
    const uint32_t ar  = (uint32_t)(wm * 64 + (lane & 15));
    const uint32_t as  = (uint32_t)(lane >> 4);
    const uint32_t br4 = (uint32_t)(BM + wn * 64 + ((lane >> 4) << 3) + x7);
    const uint32_t bs4 = (uint32_t)((lane >> 3) & 1);
    uint32_t aoff[4], boff[4];
    #pragma unroll
    for (int kk = 0; kk < 4; kk++) {
        aoff[kk] = (uint32_t)(((2 * kk + (int)as)  ^ x7) << 4);
        boff[kk] = (uint32_t)(((2 * kk + (int)bs4) ^ x7) << 4);
    }

    float acc[4][8][4];
    #pragma unroll
    for (int i = 0; i < 4; i++)
        #pragma unroll
        for (int j = 0; j < 8; j++)
            #pragma unroll
            for (int q = 0; q < 4; q++) acc[i][j][q] = 0.0f;

    #define LD_FRAGS(kk, A, B)                                                        \
        do {                                                                          \
            _Pragma("unroll")                                                         \
            for (int mi = 0; mi < 4; mi++) {                                          \
                uint32_t _ad = sS + (ar + (uint32_t)(mi * 16)) * ROWB + aoff[kk];     \
                asm volatile(                                                         \
                    "ldmatrix.sync.aligned.m8n8.x4.shared.b16 {%0,%1,%2,%3}, [%4];"   \
                    : "=r"(A[mi][0]), "=r"(A[mi][1]), "=r"(A[mi][2]), "=r"(A[mi][3])  \
                    : "r"(_ad));                                                      \
            }                                                                         \
            _Pragma("unroll")                                                         \
            for (int njp = 0; njp < 4; njp++) {                                       \
                uint32_t _bd = sS + (br4 + (uint32_t)(njp * 16)) * ROWB + boff[kk];   \
                asm volatile(                                                         \
                    "ldmatrix.sync.aligned.m8n8.x4.shared.b16 {%0,%1,%2,%3}, [%4];"   \
                    : "=r"(B[2*njp][0]), "=r"(B[2*njp][1]),                           \
                      "=r"(B[2*njp+1][0]), "=r"(B[2*njp+1][1])                        \
                    : "r"(_bd));                                                      \
            }                                                                         \
        } while (0)

    #define DO_MMAS(A, B)                                                             \
        do {                                                                          \
            _Pragma("unroll")                                                         \
            for (int mi = 0; mi < 4; mi++)                                            \
                _Pragma("unroll")                                                     \
                for (int nj = 0; nj < 8; nj++) {                                      \
                    float* cc = acc[mi][nj];                                          \
                    asm volatile(                                                     \
                        "mma.sync.aligned.m16n8k16.row.col.f32.f16.f16.f32 "          \
                        "{%0,%1,%2,%3}, {%4,%5,%6,%7}, {%8,%9}, {%0,%1,%2,%3};\n"     \
                        : "+f"(cc[0]), "+f"(cc[1]), "+f"(cc[2]), "+f"(cc[3])          \
                        : "r"(A[mi][0]), "r"(A[mi][1]), "r"(A[mi][2]), "r"(A[mi][3]), \
                          "r"(B[nj][0]), "r"(B[nj][1]));                              \
                }                                                                     \
        } while (0)

    __syncthreads();   // s_tok/s_gate visible

    #pragma unroll 1
    for (int it = 0; it < KITERS; it++) {
        // 3 groups outstanding {it,it+1,it+2}; drain group it
        asm volatile("cp.async.wait_group 2;" ::: "memory");
        __syncthreads();   // all warps past iter it-1 -> stage (it+3)%4 free; stage it ready

        if (it + 3 < KITERS) LOAD_STAGE((it + 3) % STAGES, it + 3);
        asm volatile("cp.async.commit_group;" ::: "memory");

        const int st = it % STAGES;
        const uint32_t sS = smb + (uint32_t)st * STAGE_BYTES;

        uint32_t a0[4][4], b0[8][2], a1[4][4], b1[8][2];
        LD_FRAGS(0, a0, b0);
        LD_FRAGS(1, a1, b1);
        DO_MMAS(a0, b0);
        LD_FRAGS(2, a0, b0);
        DO_MMAS(a1, b1);
        LD_FRAGS(3, a1, b1);
        DO_MMAS(a0, b0);
        DO_MMAS(a1, b1);
    }

    // ---- epilogue: gate-scaled atomic accumulate into out ----
    #pragma unroll
    for (int mi = 0; mi < 4; mi++) {
        #pragma unroll
        for (int half = 0; half < 2; half++) {
            const int r = wm * 64 + mi * 16 + g4 + half * 8;
            const int p = row0 + r;
            if (p < end) {
                const float g = s_gate[r];
                float* orow = out + (size_t)s_tok[r] * D_OUT + n0;
                #pragma unroll
                for (int nj = 0; nj < 8; nj++) {
                    const int col = wn * 64 + nj * 8 + 2 * tg;
                    atomicAdd(&orow[col    ], g * acc[mi][nj][half * 2 + 0]);
                    atomicAdd(&orow[col + 1], g * acc[mi][nj][half * 2 + 1]);
                }
            }
        }
    }
}

// ---------------- launch ----------------
extern "C" void kernel_launch(void* const* d_in, const int* in_sizes, int n_in,
                              void* d_out, int out_size)
{
    const float* X = (const float*)d_in[0];
    const float* W = (const float*)d_in[1];
    const int *scat, *offs; const float* gates;
    if (n_in >= 8) {
        scat = (const int*)d_in[4]; offs = (const int*)d_in[6]; gates = (const float*)d_in[7];
    } else {
        scat = (const int*)d_in[3]; offs = (const int*)d_in[5]; gates = (const float*)d_in[6];
    }
    float* out = (float*)d_out;

    preproc<<<PRE_W_BLOCKS + PRE_X_BLOCKS + PRE_Z_BLOCKS, 256>>>(X, W, scat, out);

    const int dyn_smem = STAGES * STAGE_BYTES;   // 196608 B
    static bool attr_set = false;
    if (!attr_set) {
        cudaFuncSetAttribute(moe_mma, cudaFuncAttributeMaxDynamicSharedMemorySize, dyn_smem);
        attr_set = true;
    }

    dim3 grid(D_OUT / BN, N_EXP * MT);   // 8 x 256
    moe_mma<<<grid, NTHREADS, dyn_smem>>>(scat, offs, gates, out);
}